// round 14
// baseline (speedup 1.0000x reference)
#include <cuda_runtime.h>
#include <math.h>
#include <stdint.h>

#define B 8
#define T 4096
#define D 256
#define H 50
#define HP 64
#define BM 128
#define BN 64
#define NT (T / BN)
#define SCALE 0.14142135623730951f
#define LOG2E 1.4426950408889634f

__device__ uint16_t g_q[B * T * HP];   // bf16, pre-scaled by SCALE*LOG2E
__device__ uint16_t g_k[B * T * HP];   // bf16
__device__ uint16_t g_vt[B * HP * T];  // fp16, transposed [b][h][t]
__device__ float    g_wt[192 * D];     // w^T, tf32-rounded: [n=m*64+h][k]

__device__ __forceinline__ uint32_t smem_u32(const void* p) {
    uint32_t a;
    asm("{ .reg .u64 t; cvta.to.shared.u64 t, %1; cvt.u32.u64 %0, t; }" : "=r"(a) : "l"(p));
    return a;
}
__device__ __forceinline__ void ldsm4(uint32_t* r, uint32_t a) {
    asm volatile("ldmatrix.sync.aligned.m8n8.x4.shared.b16 {%0,%1,%2,%3}, [%4];"
        : "=r"(r[0]), "=r"(r[1]), "=r"(r[2]), "=r"(r[3]) : "r"(a));
}
__device__ __forceinline__ void mma_tf32(float* c, const uint32_t* a, uint32_t b0, uint32_t b1) {
    asm volatile("mma.sync.aligned.m16n8k8.row.col.f32.tf32.tf32.f32 "
        "{%0,%1,%2,%3},{%4,%5,%6,%7},{%8,%9},{%0,%1,%2,%3};"
        : "+f"(c[0]), "+f"(c[1]), "+f"(c[2]), "+f"(c[3])
        : "r"(a[0]), "r"(a[1]), "r"(a[2]), "r"(a[3]), "r"(b0), "r"(b1));
}
__device__ __forceinline__ void mma_bf16(float* c, const uint32_t* a, uint32_t b0, uint32_t b1) {
    asm volatile("mma.sync.aligned.m16n8k16.row.col.f32.bf16.bf16.f32 "
        "{%0,%1,%2,%3},{%4,%5,%6,%7},{%8,%9},{%0,%1,%2,%3};"
        : "+f"(c[0]), "+f"(c[1]), "+f"(c[2]), "+f"(c[3])
        : "r"(a[0]), "r"(a[1]), "r"(a[2]), "r"(a[3]), "r"(b0), "r"(b1));
}
__device__ __forceinline__ void mma_f16(float* c, const uint32_t* a, uint32_t b0, uint32_t b1) {
    asm volatile("mma.sync.aligned.m16n8k16.row.col.f32.f16.f16.f32 "
        "{%0,%1,%2,%3},{%4,%5,%6,%7},{%8,%9},{%0,%1,%2,%3};"
        : "+f"(c[0]), "+f"(c[1]), "+f"(c[2]), "+f"(c[3])
        : "r"(a[0]), "r"(a[1]), "r"(a[2]), "r"(a[3]), "r"(b0), "r"(b1));
}
__device__ __forceinline__ float to_tf32(float x) {
    uint32_t u;
    asm("cvt.rna.tf32.f32 %0, %1;" : "=r"(u) : "f"(x));
    return __uint_as_float(u);
}
__device__ __forceinline__ float ex2(float x) {
    float r;
    asm("ex2.approx.f32 %0, %1;" : "=f"(r) : "f"(x));
    return r;
}
__device__ __forceinline__ uint32_t pack_bf2(float lo, float hi) {
    uint32_t r;
    asm("cvt.rn.bf16x2.f32 %0, %1, %2;" : "=r"(r) : "f"(hi), "f"(lo));
    return r;
}
__device__ __forceinline__ uint32_t pack_h2(float lo, float hi) {
    uint32_t r;
    asm("cvt.rn.f16x2.f32 %0, %1, %2;" : "=r"(r) : "f"(hi), "f"(lo));
    return r;
}
__device__ __forceinline__ uint16_t f2h(float x) {
    uint16_t u;
    asm("cvt.rn.f16.f32 %0, %1;" : "=h"(u) : "f"(x));
    return u;
}
__device__ __forceinline__ void cpa16(uint32_t dst, const void* src) {
    asm volatile("cp.async.cg.shared.global [%0], [%1], 16;" :: "r"(dst), "l"(src));
}
#define CP_COMMIT() asm volatile("cp.async.commit_group;" ::: "memory")
#define CP_WAIT0()  asm volatile("cp.async.wait_group 0;" ::: "memory")

// ---------------------------------------------------------------------------
// Kernel 0: transpose + tf32-round w -> g_wt[192][256]
// ---------------------------------------------------------------------------
__global__ void __launch_bounds__(256) wtrans(const float* __restrict__ w) {
    int idx = blockIdx.x * 256 + threadIdx.x;
    int n = idx >> 8;
    int k = idx & 255;
    int m = n >> 6, h = n & 63;
    g_wt[idx] = (h < H) ? to_tf32(w[m * (D * H) + k * H + h]) : 0.f;
}

// ---------------------------------------------------------------------------
// Kernel 1: QKV projection (tf32 warp-MMA), double-buffered (R12 verified).
// ---------------------------------------------------------------------------
#define NQK 192
#define XST 36
#define WST 36
#define XSB (128 * XST * 4)
#define WTB (NQK * WST * 4)
#define QSMEM (2 * XSB + 2 * WTB) // 92160

__device__ __forceinline__ void qkv_stage(char* smc, uint32_t sb, int buf,
                                          const float* __restrict__ x,
                                          int r0, int k0) {
    const int tid = threadIdx.x;
    float* xs = (float*)(smc + buf * XSB);
    #pragma unroll
    for (int i = 0; i < 4; i++) {
        int idx = tid + i * 256;
        int r = idx >> 3, c4 = idx & 7;
        float4 v = *(const float4*)(x + (size_t)(r0 + r) * D + k0 + c4 * 4);
        float* dst = xs + r * XST + c4 * 4;
        dst[0] = to_tf32(v.x); dst[1] = to_tf32(v.y);
        dst[2] = to_tf32(v.z); dst[3] = to_tf32(v.w);
    }
    const uint32_t wdst = sb + 2 * XSB + buf * WTB;
    #pragma unroll
    for (int i = 0; i < 6; i++) {
        int idx = tid + i * 256;
        int n = idx >> 3, c = idx & 7;
        cpa16(wdst + n * (WST * 4) + c * 16, g_wt + (size_t)n * D + k0 + c * 4);
    }
}

__global__ void __launch_bounds__(256) qkv_mma(const float* __restrict__ x) {
    extern __shared__ char smc[];
    const uint32_t sb = smem_u32(smc);
    const int tid  = threadIdx.x;
    const int lane = tid & 31;
    const int wp   = tid >> 5;
    const int r0   = blockIdx.x * 128;

    const uint32_t a_base = sb
        + (wp * 16 + (lane & 7) + 8 * ((lane >> 3) & 1)) * (XST * 4)
        + (lane >> 4) * 16;
    const uint32_t b_base = sb + 2 * XSB
        + ((lane & 7) + 8 * (lane >> 4)) * (WST * 4)
        + ((lane >> 3) & 1) * 16;

    float c[24][4];
    #pragma unroll
    for (int i = 0; i < 24; i++)
        #pragma unroll
        for (int e = 0; e < 4; e++) c[i][e] = 0.f;

    qkv_stage(smc, sb, 0, x, r0, 0);
    CP_COMMIT();
    CP_WAIT0();
    __syncthreads();

    for (int i = 0; i < 8; i++) {
        const int cur = i & 1;
        if (i < 7) {
            qkv_stage(smc, sb, cur ^ 1, x, r0, (i + 1) * 32);
            CP_COMMIT();
        }

        const uint32_t a_addr = a_base + cur * XSB;
        const uint32_t b_addr = b_base + cur * WTB;
        #pragma unroll
        for (int ks = 0; ks < 4; ks++) {
            uint32_t qa[4];
            ldsm4(qa, a_addr + ks * 32);
            #pragma unroll
            for (int np = 0; np < 12; np++) {
                uint32_t bb[4];
                ldsm4(bb, b_addr + np * (16 * WST * 4) + ks * 32);
                mma_tf32(c[2 * np],     qa, bb[0], bb[1]);
                mma_tf32(c[2 * np + 1], qa, bb[2], bb[3]);
            }
        }

        CP_WAIT0();
        __syncthreads();
    }

    const int pr = lane >> 2, pc = 2 * (lane & 3);
    const int row = r0 + wp * 16 + pr;
    const int bb_ = row >> 12;
    const int t_  = row & (T - 1);
    #pragma unroll
    for (int nt = 0; nt < 24; nt++) {
        int n = nt * 8 + pc;
        int m = n >> 6, h = n & 63;
        if (m == 2) {                       // V transposed, fp16
            uint16_t* vt = g_vt + ((size_t)bb_ * HP + h) * T + t_;
            vt[0]     = f2h(c[nt][0]);
            vt[T]     = f2h(c[nt][1]);
            vt[8]     = f2h(c[nt][2]);
            vt[T + 8] = f2h(c[nt][3]);
        } else {                            // Q (scale*log2e) / K packed bf16
            float s = (m == 0) ? (SCALE * LOG2E) : 1.f;
            uint16_t* dst = (m == 0) ? g_q : g_k;
            *(uint32_t*)(dst + (size_t)row * HP + h) =
                pack_bf2(c[nt][0] * s, c[nt][1] * s);
            *(uint32_t*)(dst + (size_t)(row + 8) * HP + h) =
                pack_bf2(c[nt][2] * s, c[nt][3] * s);
        }
    }
}

// ---------------------------------------------------------------------------
// Kernel 2: flash attention. S = QK^T bf16 m16n8k16; p = 2^S via ex2;
// PV = fp16 m16n8k16. n-tile-pair-outer S loop: scores for one PV k-chunk
// are finished and packed immediately -> 16 live score regs instead of 64,
// enabling 3 CTAs/SM.
// ---------------------------------------------------------------------------
#define KSTB 144
#define KBUFB (64 * KSTB)        // 9216
#define VSTB 144
#define VBUF (64 * VSTB)         // 9216
#define KOFF 0
#define VOFF (2 * KBUFB)         // 18432
#define SMEMSZ (VOFF + 2 * VBUF) // 36864

__device__ __forceinline__ void load_kv(uint32_t ksm_b, uint32_t vsm_b, int buf,
                                        int t, int b) {
    const int tid = threadIdx.x;
    const uint16_t* kg  = g_k  + ((size_t)b * T + t * BN) * HP;
    const uint16_t* vtg = g_vt + (size_t)b * HP * T + t * BN;
    const uint32_t kdst = ksm_b + buf * KBUFB;
    const uint32_t vdst = vsm_b + buf * VBUF;
    #pragma unroll
    for (int j = 0; j < 4; j++) {
        int i = tid + j * 128;
        int n = i >> 3, c = i & 7;
        cpa16(kdst + n * KSTB + c * 16, kg + n * HP + c * 8);
    }
    #pragma unroll
    for (int j = 0; j < 4; j++) {
        int i = tid + j * 128;
        int n = i >> 3, c = i & 7;
        cpa16(vdst + n * VSTB + c * 16, vtg + (size_t)n * T + c * 8);
    }
}

__global__ void __launch_bounds__(128, 3) attn_tc(float* __restrict__ out) {
    extern __shared__ char smc[];
    const int tid  = threadIdx.x;
    const int lane = tid & 31;
    const int w    = tid >> 5;
    const int tig  = lane & 3;
    const int pr   = lane >> 2;

    const int b = blockIdx.x >> 5;
    const int row_blk = blockIdx.x * BM;

    const uint32_t ksm_b = smem_u32(smc + KOFF);
    const uint32_t vsm_b = smem_u32(smc + VOFF);
    const uint32_t kb_off = ((lane & 7) + 8 * (lane >> 4)) * KSTB
                          + ((lane >> 3) & 1) * 16;
    const uint32_t vb_off = ((lane & 7) + 8 * (lane >> 4)) * VSTB
                          + ((lane >> 3) & 1) * 16;

    // ---- stage Q (bf16) through K region, grab A-frags ----
    {
        const uint16_t* qb = g_q + (size_t)(row_blk + tid) * HP;
        char* dst = smc + tid * KSTB;
        #pragma unroll
        for (int j = 0; j < 8; j++)
            *(float4*)(dst + j * 16) = *(const float4*)(qb + j * 8);
    }
    __syncthreads();
    uint32_t qa[2][4][4];
    {
        const uint32_t a_addr = ksm_b
            + (w * 32 + (lane & 7) + 8 * ((lane >> 3) & 1)) * KSTB
            + (lane >> 4) * 16;
        #pragma unroll
        for (int msub = 0; msub < 2; msub++)
            #pragma unroll
            for (int kc = 0; kc < 4; kc++)
                ldsm4(qa[msub][kc], a_addr + msub * (16 * KSTB) + kc * 32);
    }
    __syncthreads();

    float z[2][7][4];
    #pragma unroll
    for (int i = 0; i < 2; i++)
        #pragma unroll
        for (int j = 0; j < 7; j++)
            #pragma unroll
            for (int e = 0; e < 4; e++) z[i][j][e] = 0.f;
    float lacc[2][2] = {{0.f, 0.f}, {0.f, 0.f}};

    load_kv(ksm_b, vsm_b, 0, 0, b);
    CP_COMMIT();
    CP_WAIT0();
    __syncthreads();

    for (int t = 0; t < NT; t++) {
        const int cur = t & 1;
        if (t + 1 < NT) load_kv(ksm_b, vsm_b, cur ^ 1, t + 1, b);
        CP_COMMIT();

        const uint32_t kb_addr = ksm_b + cur * KBUFB + kb_off;
        const uint32_t vb_addr = vsm_b + cur * VBUF + vb_off;

        // ---- S + softmax, one n-tile pair (= one PV k-chunk) at a time ----
        uint32_t pp[2][4][4];
        #pragma unroll
        for (int nb = 0; nb < 4; nb++) {
            float scl[2][2][4];
            #pragma unroll
            for (int i = 0; i < 2; i++)
                #pragma unroll
                for (int j = 0; j < 2; j++)
                    #pragma unroll
                    for (int e = 0; e < 4; e++) scl[i][j][e] = 0.f;

            #pragma unroll
            for (int kc = 0; kc < 4; kc++) {
                uint32_t bb[4];
                ldsm4(bb, kb_addr + nb * (16 * KSTB) + kc * 32);
                #pragma unroll
                for (int msub = 0; msub < 2; msub++) {
                    mma_bf16(scl[msub][0], qa[msub][kc], bb[0], bb[1]);
                    mma_bf16(scl[msub][1], qa[msub][kc], bb[2], bb[3]);
                }
            }

            // p = 2^S, pack straight into fp16 PV A-frags (k-chunk = nb)
            #pragma unroll
            for (int msub = 0; msub < 2; msub++) {
                float p0 = ex2(scl[msub][0][0]);
                float p1 = ex2(scl[msub][0][1]);
                float p2 = ex2(scl[msub][0][2]);
                float p3 = ex2(scl[msub][0][3]);
                float p4 = ex2(scl[msub][1][0]);
                float p5 = ex2(scl[msub][1][1]);
                float p6 = ex2(scl[msub][1][2]);
                float p7 = ex2(scl[msub][1][3]);
                lacc[msub][0] += (p0 + p1) + (p4 + p5);
                lacc[msub][1] += (p2 + p3) + (p6 + p7);
                pp[msub][nb][0] = pack_h2(p0, p1);
                pp[msub][nb][1] = pack_h2(p2, p3);
                pp[msub][nb][2] = pack_h2(p4, p5);
                pp[msub][nb][3] = pack_h2(p6, p7);
            }
        }

        // ---- Z += P V^T (fp16 m16n8k16) ----
        #pragma unroll
        for (int kc = 0; kc < 4; kc++) {
            #pragma unroll
            for (int np = 0; np < 4; np++) {
                uint32_t bb[4];
                ldsm4(bb, vb_addr + np * (16 * VSTB) + kc * 32);
                #pragma unroll
                for (int msub = 0; msub < 2; msub++) {
                    mma_f16(z[msub][2 * np], pp[msub][kc], bb[0], bb[1]);
                    if (np < 3)
                        mma_f16(z[msub][2 * np + 1], pp[msub][kc], bb[2], bb[3]);
                }
            }
        }

        CP_WAIT0();
        __syncthreads();
    }

    // ---- l reduction within quad; output ----
    #pragma unroll
    for (int msub = 0; msub < 2; msub++) {
        float l0 = lacc[msub][0], l1 = lacc[msub][1];
        l0 += __shfl_xor_sync(0xffffffffu, l0, 1);
        l0 += __shfl_xor_sync(0xffffffffu, l0, 2);
        l1 += __shfl_xor_sync(0xffffffffu, l1, 1);
        l1 += __shfl_xor_sync(0xffffffffu, l1, 2);
        const float il0 = 1.f / l0;
        const float il1 = 1.f / l1;

        const int pc = 2 * tig;
        const int m0 = row_blk + w * 32 + msub * 16 + pr;
        #pragma unroll
        for (int nt = 0; nt < 7; nt++) {
            int h = nt * 8 + pc;
            if (h <= 48) {
                *(float2*)(out + (size_t)m0 * H + h) =
                    make_float2(z[msub][nt][0] * il0, z[msub][nt][1] * il0);
                *(float2*)(out + (size_t)(m0 + 8) * H + h) =
                    make_float2(z[msub][nt][2] * il1, z[msub][nt][3] * il1);
            }
        }
    }
}

// ---------------------------------------------------------------------------
extern "C" void kernel_launch(void* const* d_in, const int* in_sizes, int n_in,
                              void* d_out, int out_size) {
    const float* x = (const float*)d_in[0];
    const float* w = (const float*)d_in[1];
    float* out = (float*)d_out;

    static int configured = 0;
    if (!configured) {
        cudaFuncSetAttribute(attn_tc, cudaFuncAttributeMaxDynamicSharedMemorySize, SMEMSZ);
        cudaFuncSetAttribute(qkv_mma, cudaFuncAttributeMaxDynamicSharedMemorySize, QSMEM);
        configured = 1;
    }

    wtrans<<<NQK, 256>>>(w);
    qkv_mma<<<(B * T) / 128, 256, QSMEM>>>(x);
    attn_tc<<<(B * T) / BM, 128, SMEMSZ>>>(out);
}

// round 15
// speedup vs baseline: 1.1147x; 1.1147x over previous
#include <cuda_runtime.h>
#include <math.h>
#include <stdint.h>

#define B 8
#define T 4096
#define D 256
#define H 50
#define HP 64
#define BM 128
#define BN 64
#define NT (T / BN)
#define SCALE 0.14142135623730951f
#define LOG2E 1.4426950408889634f

__device__ uint16_t g_q[B * T * HP];   // bf16, pre-scaled by SCALE*LOG2E
__device__ uint16_t g_k[B * T * HP];   // bf16
__device__ uint16_t g_vt[B * HP * T];  // fp16, transposed [b][h][t]
__device__ float    g_wt[192 * D];     // w^T, tf32-rounded: [n=m*64+h][k]

__device__ __forceinline__ uint32_t smem_u32(const void* p) {
    uint32_t a;
    asm("{ .reg .u64 t; cvta.to.shared.u64 t, %1; cvt.u32.u64 %0, t; }" : "=r"(a) : "l"(p));
    return a;
}
__device__ __forceinline__ void ldsm4(uint32_t* r, uint32_t a) {
    asm volatile("ldmatrix.sync.aligned.m8n8.x4.shared.b16 {%0,%1,%2,%3}, [%4];"
        : "=r"(r[0]), "=r"(r[1]), "=r"(r[2]), "=r"(r[3]) : "r"(a));
}
__device__ __forceinline__ void mma_tf32(float* c, const uint32_t* a, uint32_t b0, uint32_t b1) {
    asm volatile("mma.sync.aligned.m16n8k8.row.col.f32.tf32.tf32.f32 "
        "{%0,%1,%2,%3},{%4,%5,%6,%7},{%8,%9},{%0,%1,%2,%3};"
        : "+f"(c[0]), "+f"(c[1]), "+f"(c[2]), "+f"(c[3])
        : "r"(a[0]), "r"(a[1]), "r"(a[2]), "r"(a[3]), "r"(b0), "r"(b1));
}
__device__ __forceinline__ void mma_bf16(float* c, const uint32_t* a, uint32_t b0, uint32_t b1) {
    asm volatile("mma.sync.aligned.m16n8k16.row.col.f32.bf16.bf16.f32 "
        "{%0,%1,%2,%3},{%4,%5,%6,%7},{%8,%9},{%0,%1,%2,%3};"
        : "+f"(c[0]), "+f"(c[1]), "+f"(c[2]), "+f"(c[3])
        : "r"(a[0]), "r"(a[1]), "r"(a[2]), "r"(a[3]), "r"(b0), "r"(b1));
}
__device__ __forceinline__ void mma_f16(float* c, const uint32_t* a, uint32_t b0, uint32_t b1) {
    asm volatile("mma.sync.aligned.m16n8k16.row.col.f32.f16.f16.f32 "
        "{%0,%1,%2,%3},{%4,%5,%6,%7},{%8,%9},{%0,%1,%2,%3};"
        : "+f"(c[0]), "+f"(c[1]), "+f"(c[2]), "+f"(c[3])
        : "r"(a[0]), "r"(a[1]), "r"(a[2]), "r"(a[3]), "r"(b0), "r"(b1));
}
__device__ __forceinline__ float to_tf32(float x) {
    uint32_t u;
    asm("cvt.rna.tf32.f32 %0, %1;" : "=r"(u) : "f"(x));
    return __uint_as_float(u);
}
__device__ __forceinline__ float ex2(float x) {
    float r;
    asm("ex2.approx.f32 %0, %1;" : "=f"(r) : "f"(x));
    return r;
}
__device__ __forceinline__ uint32_t pack_bf2(float lo, float hi) {
    uint32_t r;
    asm("cvt.rn.bf16x2.f32 %0, %1, %2;" : "=r"(r) : "f"(hi), "f"(lo));
    return r;
}
__device__ __forceinline__ uint32_t pack_h2(float lo, float hi) {
    uint32_t r;
    asm("cvt.rn.f16x2.f32 %0, %1, %2;" : "=r"(r) : "f"(hi), "f"(lo));
    return r;
}
__device__ __forceinline__ uint16_t f2h(float x) {
    uint16_t u;
    asm("cvt.rn.f16.f32 %0, %1;" : "=h"(u) : "f"(x));
    return u;
}
__device__ __forceinline__ void cpa16(uint32_t dst, const void* src) {
    asm volatile("cp.async.cg.shared.global [%0], [%1], 16;" :: "r"(dst), "l"(src));
}
#define CP_COMMIT() asm volatile("cp.async.commit_group;" ::: "memory")
#define CP_WAIT0()  asm volatile("cp.async.wait_group 0;" ::: "memory")
#define CP_WAIT1()  asm volatile("cp.async.wait_group 1;" ::: "memory")

// ---------------------------------------------------------------------------
// Kernel 0: transpose + tf32-round w -> g_wt[192][256]
// ---------------------------------------------------------------------------
__global__ void __launch_bounds__(256) wtrans(const float* __restrict__ w) {
    int idx = blockIdx.x * 256 + threadIdx.x;
    int n = idx >> 8;
    int k = idx & 255;
    int m = n >> 6, h = n & 63;
    g_wt[idx] = (h < H) ? to_tf32(w[m * (D * H) + k * H + h]) : 0.f;
}

// ---------------------------------------------------------------------------
// Kernel 1: QKV projection (tf32 warp-MMA), double-buffered (R12 verified).
// ---------------------------------------------------------------------------
#define NQK 192
#define XST 36
#define WST 36
#define XSB (128 * XST * 4)
#define WTB (NQK * WST * 4)
#define QSMEM (2 * XSB + 2 * WTB) // 92160

__device__ __forceinline__ void qkv_stage(char* smc, uint32_t sb, int buf,
                                          const float* __restrict__ x,
                                          int r0, int k0) {
    const int tid = threadIdx.x;
    float* xs = (float*)(smc + buf * XSB);
    #pragma unroll
    for (int i = 0; i < 4; i++) {
        int idx = tid + i * 256;
        int r = idx >> 3, c4 = idx & 7;
        float4 v = *(const float4*)(x + (size_t)(r0 + r) * D + k0 + c4 * 4);
        float* dst = xs + r * XST + c4 * 4;
        dst[0] = to_tf32(v.x); dst[1] = to_tf32(v.y);
        dst[2] = to_tf32(v.z); dst[3] = to_tf32(v.w);
    }
    const uint32_t wdst = sb + 2 * XSB + buf * WTB;
    #pragma unroll
    for (int i = 0; i < 6; i++) {
        int idx = tid + i * 256;
        int n = idx >> 3, c = idx & 7;
        cpa16(wdst + n * (WST * 4) + c * 16, g_wt + (size_t)n * D + k0 + c * 4);
    }
}

__global__ void __launch_bounds__(256) qkv_mma(const float* __restrict__ x) {
    extern __shared__ char smc[];
    const uint32_t sb = smem_u32(smc);
    const int tid  = threadIdx.x;
    const int lane = tid & 31;
    const int wp   = tid >> 5;
    const int r0   = blockIdx.x * 128;

    const uint32_t a_base = sb
        + (wp * 16 + (lane & 7) + 8 * ((lane >> 3) & 1)) * (XST * 4)
        + (lane >> 4) * 16;
    const uint32_t b_base = sb + 2 * XSB
        + ((lane & 7) + 8 * (lane >> 4)) * (WST * 4)
        + ((lane >> 3) & 1) * 16;

    float c[24][4];
    #pragma unroll
    for (int i = 0; i < 24; i++)
        #pragma unroll
        for (int e = 0; e < 4; e++) c[i][e] = 0.f;

    qkv_stage(smc, sb, 0, x, r0, 0);
    CP_COMMIT();
    CP_WAIT0();
    __syncthreads();

    for (int i = 0; i < 8; i++) {
        const int cur = i & 1;
        if (i < 7) {
            qkv_stage(smc, sb, cur ^ 1, x, r0, (i + 1) * 32);
            CP_COMMIT();
        }

        const uint32_t a_addr = a_base + cur * XSB;
        const uint32_t b_addr = b_base + cur * WTB;
        #pragma unroll
        for (int ks = 0; ks < 4; ks++) {
            uint32_t qa[4];
            ldsm4(qa, a_addr + ks * 32);
            #pragma unroll
            for (int np = 0; np < 12; np++) {
                uint32_t bb[4];
                ldsm4(bb, b_addr + np * (16 * WST * 4) + ks * 32);
                mma_tf32(c[2 * np],     qa, bb[0], bb[1]);
                mma_tf32(c[2 * np + 1], qa, bb[2], bb[3]);
            }
        }

        CP_WAIT0();
        __syncthreads();
    }

    const int pr = lane >> 2, pc = 2 * (lane & 3);
    const int row = r0 + wp * 16 + pr;
    const int bb_ = row >> 12;
    const int t_  = row & (T - 1);
    #pragma unroll
    for (int nt = 0; nt < 24; nt++) {
        int n = nt * 8 + pc;
        int m = n >> 6, h = n & 63;
        if (m == 2) {                       // V transposed, fp16
            uint16_t* vt = g_vt + ((size_t)bb_ * HP + h) * T + t_;
            vt[0]     = f2h(c[nt][0]);
            vt[T]     = f2h(c[nt][1]);
            vt[8]     = f2h(c[nt][2]);
            vt[T + 8] = f2h(c[nt][3]);
        } else {                            // Q (scale*log2e) / K packed bf16
            float s = (m == 0) ? (SCALE * LOG2E) : 1.f;
            uint16_t* dst = (m == 0) ? g_q : g_k;
            *(uint32_t*)(dst + (size_t)row * HP + h) =
                pack_bf2(c[nt][0] * s, c[nt][1] * s);
            *(uint32_t*)(dst + (size_t)(row + 8) * HP + h) =
                pack_bf2(c[nt][2] * s, c[nt][3] * s);
        }
    }
}

// ---------------------------------------------------------------------------
// Kernel 2: flash attention (R13 body, verified 138.2us) with a 3-stage
// cp.async pipeline: at tile t we issue loads for t+2 and wait_group(1),
// so t+1's load has a full tile of slack instead of blocking the barrier.
// S = QK^T bf16 m16n8k16; p = 2^S via ex2; PV = fp16 m16n8k16.
// smem: K bf16 3x[64][72], V^T fp16 3x[64][72] = 55296 B, 2 CTAs/SM.
// ---------------------------------------------------------------------------
#define KSTB 144
#define KBUFB (64 * KSTB)        // 9216
#define VSTB 144
#define VBUF (64 * VSTB)         // 9216
#define NSTG 3
#define KOFF 0
#define VOFF (NSTG * KBUFB)      // 27648
#define SMEMSZ (VOFF + NSTG * VBUF) // 55296

__device__ __forceinline__ void load_kv(uint32_t ksm_b, uint32_t vsm_b, int buf,
                                        int t, int b) {
    const int tid = threadIdx.x;
    const uint16_t* kg  = g_k  + ((size_t)b * T + t * BN) * HP;
    const uint16_t* vtg = g_vt + (size_t)b * HP * T + t * BN;
    const uint32_t kdst = ksm_b + buf * KBUFB;
    const uint32_t vdst = vsm_b + buf * VBUF;
    #pragma unroll
    for (int j = 0; j < 4; j++) {
        int i = tid + j * 128;
        int n = i >> 3, c = i & 7;
        cpa16(kdst + n * KSTB + c * 16, kg + n * HP + c * 8);
    }
    #pragma unroll
    for (int j = 0; j < 4; j++) {
        int i = tid + j * 128;
        int n = i >> 3, c = i & 7;
        cpa16(vdst + n * VSTB + c * 16, vtg + (size_t)n * T + c * 8);
    }
}

__global__ void __launch_bounds__(128, 2) attn_tc(float* __restrict__ out) {
    extern __shared__ char smc[];
    const int tid  = threadIdx.x;
    const int lane = tid & 31;
    const int w    = tid >> 5;
    const int tig  = lane & 3;
    const int pr   = lane >> 2;

    const int b = blockIdx.x >> 5;
    const int row_blk = blockIdx.x * BM;

    const uint32_t ksm_b = smem_u32(smc + KOFF);
    const uint32_t vsm_b = smem_u32(smc + VOFF);
    const uint32_t kb_off = ((lane & 7) + 8 * (lane >> 4)) * KSTB
                          + ((lane >> 3) & 1) * 16;
    const uint32_t vb_off = ((lane & 7) + 8 * (lane >> 4)) * VSTB
                          + ((lane >> 3) & 1) * 16;

    // ---- stage Q (bf16) through K region (bufs 0-1), grab A-frags ----
    {
        const uint16_t* qb = g_q + (size_t)(row_blk + tid) * HP;
        char* dst = smc + tid * KSTB;
        #pragma unroll
        for (int j = 0; j < 8; j++)
            *(float4*)(dst + j * 16) = *(const float4*)(qb + j * 8);
    }
    __syncthreads();
    uint32_t qa[2][4][4];
    {
        const uint32_t a_addr = ksm_b
            + (w * 32 + (lane & 7) + 8 * ((lane >> 3) & 1)) * KSTB
            + (lane >> 4) * 16;
        #pragma unroll
        for (int msub = 0; msub < 2; msub++)
            #pragma unroll
            for (int kc = 0; kc < 4; kc++)
                ldsm4(qa[msub][kc], a_addr + msub * (16 * KSTB) + kc * 32);
    }
    __syncthreads();

    float z[2][7][4];
    #pragma unroll
    for (int i = 0; i < 2; i++)
        #pragma unroll
        for (int j = 0; j < 7; j++)
            #pragma unroll
            for (int e = 0; e < 4; e++) z[i][j][e] = 0.f;
    float lacc[2][2] = {{0.f, 0.f}, {0.f, 0.f}};

    // ---- 3-stage pipeline prologue: tiles 0 and 1 in flight ----
    load_kv(ksm_b, vsm_b, 0, 0, b);
    CP_COMMIT();
    load_kv(ksm_b, vsm_b, 1, 1, b);
    CP_COMMIT();
    CP_WAIT1();              // tile 0 resident; tile 1 may be in flight
    __syncthreads();

    int buf = 0;             // buffer of the current tile (t % 3)
    for (int t = 0; t < NT; t++) {
        if (t + 2 < NT) {
            // reuses buffer (t-1)%3: all its readers passed last barrier
            int nb_ = buf - 1 + ((buf == 0) ? 3 : 0);
            load_kv(ksm_b, vsm_b, nb_, t + 2, b);
            CP_COMMIT();
        }

        const uint32_t kb_addr = ksm_b + buf * KBUFB + kb_off;
        const uint32_t vb_addr = vsm_b + buf * VBUF + vb_off;

        // ---- S = Q K^T (bf16 k16) ----
        float sc[2][8][4];
        #pragma unroll
        for (int i = 0; i < 2; i++)
            #pragma unroll
            for (int j = 0; j < 8; j++)
                #pragma unroll
                for (int e = 0; e < 4; e++) sc[i][j][e] = 0.f;

        #pragma unroll
        for (int kc = 0; kc < 4; kc++) {
            #pragma unroll
            for (int nb = 0; nb < 4; nb++) {
                uint32_t bb[4];
                ldsm4(bb, kb_addr + nb * (16 * KSTB) + kc * 32);
                #pragma unroll
                for (int msub = 0; msub < 2; msub++) {
                    mma_bf16(sc[msub][2 * nb],     qa[msub][kc], bb[0], bb[1]);
                    mma_bf16(sc[msub][2 * nb + 1], qa[msub][kc], bb[2], bb[3]);
                }
            }
        }

        // ---- softmax p = 2^S, pack straight into fp16 A-frags ----
        uint32_t pp[2][4][4];
        #pragma unroll
        for (int msub = 0; msub < 2; msub++)
            #pragma unroll
            for (int kc = 0; kc < 4; kc++) {
                float p0 = ex2(sc[msub][2 * kc][0]);
                float p1 = ex2(sc[msub][2 * kc][1]);
                float p2 = ex2(sc[msub][2 * kc][2]);
                float p3 = ex2(sc[msub][2 * kc][3]);
                float p4 = ex2(sc[msub][2 * kc + 1][0]);
                float p5 = ex2(sc[msub][2 * kc + 1][1]);
                float p6 = ex2(sc[msub][2 * kc + 1][2]);
                float p7 = ex2(sc[msub][2 * kc + 1][3]);
                lacc[msub][0] += (p0 + p1) + (p4 + p5);
                lacc[msub][1] += (p2 + p3) + (p6 + p7);
                pp[msub][kc][0] = pack_h2(p0, p1);
                pp[msub][kc][1] = pack_h2(p2, p3);
                pp[msub][kc][2] = pack_h2(p4, p5);
                pp[msub][kc][3] = pack_h2(p6, p7);
            }

        // ---- Z += P V^T (fp16 m16n8k16) ----
        #pragma unroll
        for (int kc = 0; kc < 4; kc++) {
            #pragma unroll
            for (int np = 0; np < 4; np++) {
                uint32_t bb[4];
                ldsm4(bb, vb_addr + np * (16 * VSTB) + kc * 32);
                #pragma unroll
                for (int msub = 0; msub < 2; msub++) {
                    mma_f16(z[msub][2 * np], pp[msub][kc], bb[0], bb[1]);
                    if (np < 3)
                        mma_f16(z[msub][2 * np + 1], pp[msub][kc], bb[2], bb[3]);
                }
            }
        }

        CP_WAIT1();          // next tile's buffer resident; t+2 may fly on
        __syncthreads();
        buf = (buf == 2) ? 0 : buf + 1;
    }

    // ---- l reduction within quad; output ----
    #pragma unroll
    for (int msub = 0; msub < 2; msub++) {
        float l0 = lacc[msub][0], l1 = lacc[msub][1];
        l0 += __shfl_xor_sync(0xffffffffu, l0, 1);
        l0 += __shfl_xor_sync(0xffffffffu, l0, 2);
        l1 += __shfl_xor_sync(0xffffffffu, l1, 1);
        l1 += __shfl_xor_sync(0xffffffffu, l1, 2);
        const float il0 = 1.f / l0;
        const float il1 = 1.f / l1;

        const int pc = 2 * tig;
        const int m0 = row_blk + w * 32 + msub * 16 + pr;
        #pragma unroll
        for (int nt = 0; nt < 7; nt++) {
            int h = nt * 8 + pc;
            if (h <= 48) {
                *(float2*)(out + (size_t)m0 * H + h) =
                    make_float2(z[msub][nt][0] * il0, z[msub][nt][1] * il0);
                *(float2*)(out + (size_t)(m0 + 8) * H + h) =
                    make_float2(z[msub][nt][2] * il1, z[msub][nt][3] * il1);
            }
        }
    }
}

// ---------------------------------------------------------------------------
extern "C" void kernel_launch(void* const* d_in, const int* in_sizes, int n_in,
                              void* d_out, int out_size) {
    const float* x = (const float*)d_in[0];
    const float* w = (const float*)d_in[1];
    float* out = (float*)d_out;

    static int configured = 0;
    if (!configured) {
        cudaFuncSetAttribute(attn_tc, cudaFuncAttributeMaxDynamicSharedMemorySize, SMEMSZ);
        cudaFuncSetAttribute(qkv_mma, cudaFuncAttributeMaxDynamicSharedMemorySize, QSMEM);
        configured = 1;
    }

    wtrans<<<NQK, 256>>>(w);
    qkv_mma<<<(B * T) / 128, 256, QSMEM>>>(x);
    attn_tc<<<(B * T) / BM, 128, SMEMSZ>>>(out);
}

// round 16
// speedup vs baseline: 1.1930x; 1.0702x over previous
#include <cuda_runtime.h>
#include <math.h>
#include <stdint.h>

#define B 8
#define T 4096
#define D 256
#define H 50
#define HP 64
#define BM 128
#define BN 64
#define NT (T / BN)
#define SCALE 0.14142135623730951f
#define LOG2E 1.4426950408889634f

__device__ uint16_t g_q[B * T * HP];   // bf16, pre-scaled by SCALE*LOG2E
__device__ uint16_t g_k[B * T * HP];   // bf16
__device__ uint16_t g_vt[B * HP * T];  // fp16, transposed [b][h][t]; row 50 = 1.0
__device__ float    g_wt[192 * D];     // w^T, tf32-rounded

__device__ __forceinline__ uint32_t smem_u32(const void* p) {
    uint32_t a;
    asm("{ .reg .u64 t; cvta.to.shared.u64 t, %1; cvt.u32.u64 %0, t; }" : "=r"(a) : "l"(p));
    return a;
}
__device__ __forceinline__ void ldsm4(uint32_t* r, uint32_t a) {
    asm volatile("ldmatrix.sync.aligned.m8n8.x4.shared.b16 {%0,%1,%2,%3}, [%4];"
        : "=r"(r[0]), "=r"(r[1]), "=r"(r[2]), "=r"(r[3]) : "r"(a));
}
__device__ __forceinline__ void mma_tf32(float* c, const uint32_t* a, uint32_t b0, uint32_t b1) {
    asm volatile("mma.sync.aligned.m16n8k8.row.col.f32.tf32.tf32.f32 "
        "{%0,%1,%2,%3},{%4,%5,%6,%7},{%8,%9},{%0,%1,%2,%3};"
        : "+f"(c[0]), "+f"(c[1]), "+f"(c[2]), "+f"(c[3])
        : "r"(a[0]), "r"(a[1]), "r"(a[2]), "r"(a[3]), "r"(b0), "r"(b1));
}
__device__ __forceinline__ void mma_bf16(float* c, const uint32_t* a, uint32_t b0, uint32_t b1) {
    asm volatile("mma.sync.aligned.m16n8k16.row.col.f32.bf16.bf16.f32 "
        "{%0,%1,%2,%3},{%4,%5,%6,%7},{%8,%9},{%0,%1,%2,%3};"
        : "+f"(c[0]), "+f"(c[1]), "+f"(c[2]), "+f"(c[3])
        : "r"(a[0]), "r"(a[1]), "r"(a[2]), "r"(a[3]), "r"(b0), "r"(b1));
}
__device__ __forceinline__ void mma_f16(float* c, const uint32_t* a, uint32_t b0, uint32_t b1) {
    asm volatile("mma.sync.aligned.m16n8k16.row.col.f32.f16.f16.f32 "
        "{%0,%1,%2,%3},{%4,%5,%6,%7},{%8,%9},{%0,%1,%2,%3};"
        : "+f"(c[0]), "+f"(c[1]), "+f"(c[2]), "+f"(c[3])
        : "r"(a[0]), "r"(a[1]), "r"(a[2]), "r"(a[3]), "r"(b0), "r"(b1));
}
__device__ __forceinline__ float to_tf32(float x) {
    uint32_t u;
    asm("cvt.rna.tf32.f32 %0, %1;" : "=r"(u) : "f"(x));
    return __uint_as_float(u);
}
__device__ __forceinline__ uint32_t pack_bf2(float lo, float hi) {
    uint32_t r;
    asm("cvt.rn.bf16x2.f32 %0, %1, %2;" : "=r"(r) : "f"(hi), "f"(lo));
    return r;
}
__device__ __forceinline__ uint32_t pack_h2(float lo, float hi) {
    uint32_t r;
    asm("cvt.rn.f16x2.f32 %0, %1, %2;" : "=r"(r) : "f"(hi), "f"(lo));
    return r;
}
__device__ __forceinline__ uint32_t h2ex2(uint32_t x) {
    uint32_t r;
    asm("ex2.approx.f16x2 %0, %1;" : "=r"(r) : "r"(x));
    return r;
}
__device__ __forceinline__ uint16_t f2h(float x) {
    uint16_t u;
    asm("cvt.rn.f16.f32 %0, %1;" : "=h"(u) : "f"(x));
    return u;
}
__device__ __forceinline__ void cpa16(uint32_t dst, const void* src) {
    asm volatile("cp.async.cg.shared.global [%0], [%1], 16;" :: "r"(dst), "l"(src));
}
#define CP_COMMIT() asm volatile("cp.async.commit_group;" ::: "memory")
#define CP_WAIT0()  asm volatile("cp.async.wait_group 0;" ::: "memory")
#define CP_WAIT1()  asm volatile("cp.async.wait_group 1;" ::: "memory")

// ---------------------------------------------------------------------------
// Kernel 0: transpose + tf32-round w -> g_wt[192][256]
// ---------------------------------------------------------------------------
__global__ void __launch_bounds__(256) wtrans(const float* __restrict__ w) {
    int idx = blockIdx.x * 256 + threadIdx.x;
    int n = idx >> 8;
    int k = idx & 255;
    int m = n >> 6, h = n & 63;
    g_wt[idx] = (h < H) ? to_tf32(w[m * (D * H) + k * H + h]) : 0.f;
}

// ---------------------------------------------------------------------------
// Kernel 1: QKV projection (tf32 warp-MMA), double-buffered (R12 verified).
// V^T row 50 is set to 1.0 so attention's Z column 50 computes l for free.
// ---------------------------------------------------------------------------
#define NQK 192
#define XST 36
#define WST 36
#define XSB (128 * XST * 4)
#define WTB (NQK * WST * 4)
#define QSMEM (2 * XSB + 2 * WTB) // 92160

__device__ __forceinline__ void qkv_stage(char* smc, uint32_t sb, int buf,
                                          const float* __restrict__ x,
                                          int r0, int k0) {
    const int tid = threadIdx.x;
    float* xs = (float*)(smc + buf * XSB);
    #pragma unroll
    for (int i = 0; i < 4; i++) {
        int idx = tid + i * 256;
        int r = idx >> 3, c4 = idx & 7;
        float4 v = *(const float4*)(x + (size_t)(r0 + r) * D + k0 + c4 * 4);
        float* dst = xs + r * XST + c4 * 4;
        dst[0] = to_tf32(v.x); dst[1] = to_tf32(v.y);
        dst[2] = to_tf32(v.z); dst[3] = to_tf32(v.w);
    }
    const uint32_t wdst = sb + 2 * XSB + buf * WTB;
    #pragma unroll
    for (int i = 0; i < 6; i++) {
        int idx = tid + i * 256;
        int n = idx >> 3, c = idx & 7;
        cpa16(wdst + n * (WST * 4) + c * 16, g_wt + (size_t)n * D + k0 + c * 4);
    }
}

__global__ void __launch_bounds__(256) qkv_mma(const float* __restrict__ x) {
    extern __shared__ char smc[];
    const uint32_t sb = smem_u32(smc);
    const int tid  = threadIdx.x;
    const int lane = tid & 31;
    const int wp   = tid >> 5;
    const int r0   = blockIdx.x * 128;

    const uint32_t a_base = sb
        + (wp * 16 + (lane & 7) + 8 * ((lane >> 3) & 1)) * (XST * 4)
        + (lane >> 4) * 16;
    const uint32_t b_base = sb + 2 * XSB
        + ((lane & 7) + 8 * (lane >> 4)) * (WST * 4)
        + ((lane >> 3) & 1) * 16;

    float c[24][4];
    #pragma unroll
    for (int i = 0; i < 24; i++)
        #pragma unroll
        for (int e = 0; e < 4; e++) c[i][e] = 0.f;

    qkv_stage(smc, sb, 0, x, r0, 0);
    CP_COMMIT();
    CP_WAIT0();
    __syncthreads();

    for (int i = 0; i < 8; i++) {
        const int cur = i & 1;
        if (i < 7) {
            qkv_stage(smc, sb, cur ^ 1, x, r0, (i + 1) * 32);
            CP_COMMIT();
        }

        const uint32_t a_addr = a_base + cur * XSB;
        const uint32_t b_addr = b_base + cur * WTB;
        #pragma unroll
        for (int ks = 0; ks < 4; ks++) {
            uint32_t qa[4];
            ldsm4(qa, a_addr + ks * 32);
            #pragma unroll
            for (int np = 0; np < 12; np++) {
                uint32_t bb[4];
                ldsm4(bb, b_addr + np * (16 * WST * 4) + ks * 32);
                mma_tf32(c[2 * np],     qa, bb[0], bb[1]);
                mma_tf32(c[2 * np + 1], qa, bb[2], bb[3]);
            }
        }

        CP_WAIT0();
        __syncthreads();
    }

    const int pr = lane >> 2, pc = 2 * (lane & 3);
    const int row = r0 + wp * 16 + pr;
    const int bb_ = row >> 12;
    const int t_  = row & (T - 1);
    #pragma unroll
    for (int nt = 0; nt < 24; nt++) {
        int n = nt * 8 + pc;
        int m = n >> 6, h = n & 63;
        if (m == 2) {                       // V transposed, fp16; row 50 = ones
            uint16_t* vt = g_vt + ((size_t)bb_ * HP + h) * T + t_;
            if (h == 50) {
                vt[0] = 0x3C00; vt[8] = 0x3C00;       // 1.0h
            } else {
                vt[0] = f2h(c[nt][0]);
                vt[8] = f2h(c[nt][2]);
            }
            vt[T]     = f2h(c[nt][1]);
            vt[T + 8] = f2h(c[nt][3]);
        } else {                            // Q (scale*log2e) / K packed bf16
            float s = (m == 0) ? (SCALE * LOG2E) : 1.f;
            uint16_t* dst = (m == 0) ? g_q : g_k;
            *(uint32_t*)(dst + (size_t)row * HP + h) =
                pack_bf2(c[nt][0] * s, c[nt][1] * s);
            *(uint32_t*)(dst + (size_t)(row + 8) * HP + h) =
                pack_bf2(c[nt][2] * s, c[nt][3] * s);
        }
    }
}

// ---------------------------------------------------------------------------
// Kernel 2: flash attention. S = QK^T bf16; softmax = pack scores to fp16 +
// ex2.approx.f16x2 (results land directly in PV A-frag format); PV fp16.
// l is NOT accumulated: V^T row 50 = 1.0 makes Z[:,50] = sum(P) = l.
// 3-stage cp.async pipeline (R15).
// ---------------------------------------------------------------------------
#define KSTB 144
#define KBUFB (64 * KSTB)        // 9216
#define VSTB 144
#define VBUF (64 * VSTB)         // 9216
#define NSTG 3
#define KOFF 0
#define VOFF (NSTG * KBUFB)      // 27648
#define SMEMSZ (VOFF + NSTG * VBUF) // 55296

__device__ __forceinline__ void load_kv(uint32_t ksm_b, uint32_t vsm_b, int buf,
                                        int t, int b) {
    const int tid = threadIdx.x;
    const uint16_t* kg  = g_k  + ((size_t)b * T + t * BN) * HP;
    const uint16_t* vtg = g_vt + (size_t)b * HP * T + t * BN;
    const uint32_t kdst = ksm_b + buf * KBUFB;
    const uint32_t vdst = vsm_b + buf * VBUF;
    #pragma unroll
    for (int j = 0; j < 4; j++) {
        int i = tid + j * 128;
        int n = i >> 3, c = i & 7;
        cpa16(kdst + n * KSTB + c * 16, kg + n * HP + c * 8);
    }
    #pragma unroll
    for (int j = 0; j < 4; j++) {
        int i = tid + j * 128;
        int n = i >> 3, c = i & 7;
        cpa16(vdst + n * VSTB + c * 16, vtg + (size_t)n * T + c * 8);
    }
}

__global__ void __launch_bounds__(128, 2) attn_tc(float* __restrict__ out) {
    extern __shared__ char smc[];
    const int tid  = threadIdx.x;
    const int lane = tid & 31;
    const int w    = tid >> 5;
    const int tig  = lane & 3;
    const int pr   = lane >> 2;

    const int b = blockIdx.x >> 5;
    const int row_blk = blockIdx.x * BM;

    const uint32_t ksm_b = smem_u32(smc + KOFF);
    const uint32_t vsm_b = smem_u32(smc + VOFF);
    const uint32_t kb_off = ((lane & 7) + 8 * (lane >> 4)) * KSTB
                          + ((lane >> 3) & 1) * 16;
    const uint32_t vb_off = ((lane & 7) + 8 * (lane >> 4)) * VSTB
                          + ((lane >> 3) & 1) * 16;

    // ---- stage Q (bf16) through K region, grab A-frags ----
    {
        const uint16_t* qb = g_q + (size_t)(row_blk + tid) * HP;
        char* dst = smc + tid * KSTB;
        #pragma unroll
        for (int j = 0; j < 8; j++)
            *(float4*)(dst + j * 16) = *(const float4*)(qb + j * 8);
    }
    __syncthreads();
    uint32_t qa[2][4][4];
    {
        const uint32_t a_addr = ksm_b
            + (w * 32 + (lane & 7) + 8 * ((lane >> 3) & 1)) * KSTB
            + (lane >> 4) * 16;
        #pragma unroll
        for (int msub = 0; msub < 2; msub++)
            #pragma unroll
            for (int kc = 0; kc < 4; kc++)
                ldsm4(qa[msub][kc], a_addr + msub * (16 * KSTB) + kc * 32);
    }
    __syncthreads();

    float z[2][7][4];
    #pragma unroll
    for (int i = 0; i < 2; i++)
        #pragma unroll
        for (int j = 0; j < 7; j++)
            #pragma unroll
            for (int e = 0; e < 4; e++) z[i][j][e] = 0.f;

    // ---- 3-stage pipeline prologue ----
    load_kv(ksm_b, vsm_b, 0, 0, b);
    CP_COMMIT();
    load_kv(ksm_b, vsm_b, 1, 1, b);
    CP_COMMIT();
    CP_WAIT1();
    __syncthreads();

    int buf = 0;
    for (int t = 0; t < NT; t++) {
        if (t + 2 < NT) {
            int nb_ = buf - 1 + ((buf == 0) ? 3 : 0);
            load_kv(ksm_b, vsm_b, nb_, t + 2, b);
            CP_COMMIT();
        }

        const uint32_t kb_addr = ksm_b + buf * KBUFB + kb_off;
        const uint32_t vb_addr = vsm_b + buf * VBUF + vb_off;

        // ---- S = Q K^T (bf16 k16) ----
        float sc[2][8][4];
        #pragma unroll
        for (int i = 0; i < 2; i++)
            #pragma unroll
            for (int j = 0; j < 8; j++)
                #pragma unroll
                for (int e = 0; e < 4; e++) sc[i][j][e] = 0.f;

        #pragma unroll
        for (int kc = 0; kc < 4; kc++) {
            #pragma unroll
            for (int nb = 0; nb < 4; nb++) {
                uint32_t bb[4];
                ldsm4(bb, kb_addr + nb * (16 * KSTB) + kc * 32);
                #pragma unroll
                for (int msub = 0; msub < 2; msub++) {
                    mma_bf16(sc[msub][2 * nb],     qa[msub][kc], bb[0], bb[1]);
                    mma_bf16(sc[msub][2 * nb + 1], qa[msub][kc], bb[2], bb[3]);
                }
            }
        }

        // ---- softmax: pack fp16 score pairs, p = 2^s via ex2.f16x2 ----
        uint32_t pp[2][4][4];
        #pragma unroll
        for (int msub = 0; msub < 2; msub++)
            #pragma unroll
            for (int kc = 0; kc < 4; kc++) {
                pp[msub][kc][0] = h2ex2(pack_h2(sc[msub][2 * kc][0],     sc[msub][2 * kc][1]));
                pp[msub][kc][1] = h2ex2(pack_h2(sc[msub][2 * kc][2],     sc[msub][2 * kc][3]));
                pp[msub][kc][2] = h2ex2(pack_h2(sc[msub][2 * kc + 1][0], sc[msub][2 * kc + 1][1]));
                pp[msub][kc][3] = h2ex2(pack_h2(sc[msub][2 * kc + 1][2], sc[msub][2 * kc + 1][3]));
            }

        // ---- Z += P V^T (fp16 m16n8k16); col 50 accumulates l ----
        #pragma unroll
        for (int kc = 0; kc < 4; kc++) {
            #pragma unroll
            for (int np = 0; np < 4; np++) {
                uint32_t bb[4];
                ldsm4(bb, vb_addr + np * (16 * VSTB) + kc * 32);
                #pragma unroll
                for (int msub = 0; msub < 2; msub++) {
                    mma_f16(z[msub][2 * np], pp[msub][kc], bb[0], bb[1]);
                    if (np < 3)
                        mma_f16(z[msub][2 * np + 1], pp[msub][kc], bb[2], bb[3]);
                }
            }
        }

        CP_WAIT1();
        __syncthreads();
        buf = (buf == 2) ? 0 : buf + 1;
    }

    // ---- l from Z column 50 (nt=6, tig=1): one quad shfl broadcast ----
    const int lsrc = (lane & 28) | 1;
    #pragma unroll
    for (int msub = 0; msub < 2; msub++) {
        const float l0 = __shfl_sync(0xffffffffu, z[msub][6][0], lsrc);
        const float l1 = __shfl_sync(0xffffffffu, z[msub][6][2], lsrc);
        const float il0 = 1.f / l0;
        const float il1 = 1.f / l1;

        const int pc = 2 * tig;
        const int m0 = row_blk + w * 32 + msub * 16 + pr;
        #pragma unroll
        for (int nt = 0; nt < 7; nt++) {
            int h = nt * 8 + pc;
            if (h <= 48) {
                *(float2*)(out + (size_t)m0 * H + h) =
                    make_float2(z[msub][nt][0] * il0, z[msub][nt][1] * il0);
                *(float2*)(out + (size_t)(m0 + 8) * H + h) =
                    make_float2(z[msub][nt][2] * il1, z[msub][nt][3] * il1);
            }
        }
    }
}

// ---------------------------------------------------------------------------
extern "C" void kernel_launch(void* const* d_in, const int* in_sizes, int n_in,
                              void* d_out, int out_size) {
    const float* x = (const float*)d_in[0];
    const float* w = (const float*)d_in[1];
    float* out = (float*)d_out;

    static int configured = 0;
    if (!configured) {
        cudaFuncSetAttribute(attn_tc, cudaFuncAttributeMaxDynamicSharedMemorySize, SMEMSZ);
        cudaFuncSetAttribute(qkv_mma, cudaFuncAttributeMaxDynamicSharedMemorySize, QSMEM);
        configured = 1;
    }

    wtrans<<<NQK, 256>>>(w);
    qkv_mma<<<(B * T) / 128, 256, QSMEM>>>(x);
    attn_tc<<<(B * T) / BM, 128, SMEMSZ>>>(out);
}